// round 8
// baseline (speedup 1.0000x reference)
#include <cuda_runtime.h>
#include <cstdint>

#define HH 256
#define WW 256
#define CC 128
#define HWSZ 65536
#define IMG (CC * HH * WW)          // 8388608 floats per frame
#define VIMG (36ull * 128 * 4096)   // transformed plane per image

// ---------------- scratch (__device__ globals; no allocations) -------------
__device__ float g_Q[2ull * IMG];
__device__ float g_KV[4ull * IMG];
__device__ float g_KVw[8ull * IMG];
__device__ float g_V[14ull * VIMG];
__device__ float g_M[14ull * VIMG];
__device__ float g_U[3ull * 36 * 128 * 128];

// ---------------- packed f32x2 helpers --------------------------------------
__device__ __forceinline__ unsigned long long pack2(float x, float y) {
    unsigned long long r;
    asm("mov.b64 %0, {%1,%2};" : "=l"(r) : "f"(x), "f"(y));
    return r;
}
__device__ __forceinline__ void unpack2(unsigned long long v, float& x, float& y) {
    asm("mov.b64 {%0,%1}, %2;" : "=f"(x), "=f"(y) : "l"(v));
}
__device__ __forceinline__ void ffma2(unsigned long long& d,
                                      unsigned long long a,
                                      unsigned long long b) {
    asm("fma.rn.f32x2 %0, %1, %2, %0;" : "+l"(d) : "l"(a), "l"(b));
}

// ---------------- cp.async helpers ------------------------------------------
__device__ __forceinline__ void cp16(uint32_t saddr, const void* g) {
    asm volatile("cp.async.cg.shared.global [%0], [%1], 16;"
                 :: "r"(saddr), "l"(g) : "memory");
}
#define CP_COMMIT() asm volatile("cp.async.commit_group;" ::: "memory")
#define CP_WAIT(n)  asm volatile("cp.async.wait_group %0;" :: "n"(n) : "memory")

__device__ __forceinline__ uint32_t smem_u32(const void* p) {
    uint32_t a;
    asm("{ .reg .u64 t; cvta.to.shared.u64 t, %1; cvt.u32.u64 %0, t; }"
        : "=r"(a) : "l"(p));
    return a;
}

// ---------------- Winograd F(4x4,3x3) transform primitives ------------------
#define BTCOMB(d0,d1,d2,d3,d4,d5,o0,o1,o2,o3,o4,o5) do {                   \
    o0 = 4.f*(d0) - 5.f*(d2) + (d4);                                       \
    float _a = (d4) - 4.f*(d2), _b = (d3) - 4.f*(d1);                      \
    o1 = _a + _b; o2 = _a - _b;                                            \
    float _c = (d4) - (d2), _e = 2.f*((d3) - (d1));                        \
    o3 = _c + _e; o4 = _c - _e;                                            \
    o5 = 4.f*(d1) - 5.f*(d3) + (d5);                                       \
} while (0)

#define ATCOMB(m0,m1,m2,m3,m4,m5,o0,o1,o2,o3) do {                         \
    float _s = (m1)+(m2), _d = (m1)-(m2), _t = (m3)+(m4), _u = (m3)-(m4);  \
    o0 = (m0) + _s + _t;                                                   \
    o1 = _d + 2.f*_u;                                                      \
    o2 = _s + 4.f*_t;                                                      \
    o3 = _d + 8.f*_u + (m5);                                               \
} while (0)

#define GCOMB(w0,w1,w2,o0,o1,o2,o3,o4,o5) do {                             \
    o0 = 0.25f*(w0);                                                       \
    float _n = -(w0) - (w2);                                               \
    o1 = (_n - (w1)) * (1.f/6.f);                                          \
    o2 = (_n + (w1)) * (1.f/6.f);                                          \
    float _p = (w0)*(1.f/24.f) + (w2)*(1.f/6.f), _q = (w1)*(1.f/12.f);     \
    o3 = _p + _q; o4 = _p - _q;                                            \
    o5 = (w2);                                                             \
} while (0)

// ---------------------------------------------------------------------------
// Filter transform, all 3 weight sets in one launch.
// ---------------------------------------------------------------------------
__global__ __launch_bounds__(256) void wino_filt3(
    const float* __restrict__ W0, const float* __restrict__ W1,
    const float* __restrict__ W2, float* __restrict__ U)
{
    int idx = blockIdx.x * 256 + threadIdx.x;
    if (idx >= 3 * 16384) return;
    int set = idx >> 14, e = idx & 16383;
    int oc = e & 127, ic = e >> 7;
    const float* W = (set == 0) ? W0 : (set == 1) ? W1 : W2;
    float* Us = U + (size_t)set * (36 * 16384);
    float w[3][3];
#pragma unroll
    for (int a = 0; a < 3; ++a)
#pragma unroll
        for (int b = 0; b < 3; ++b)
            w[a][b] = W[(size_t)oc * 1152 + ic * 9 + a * 3 + b];
    float ee[6][3];
#pragma unroll
    for (int b = 0; b < 3; ++b)
        GCOMB(w[0][b], w[1][b], w[2][b],
              ee[0][b], ee[1][b], ee[2][b], ee[3][b], ee[4][b], ee[5][b]);
#pragma unroll
    for (int i = 0; i < 6; ++i) {
        float u0, u1, u2, u3, u4, u5;
        GCOMB(ee[i][0], ee[i][1], ee[i][2], u0, u1, u2, u3, u4, u5);
        float* up = Us + (size_t)(i * 6) * 16384 + ic * 128 + oc;
        up[0 * 16384] = u0; up[1 * 16384] = u1; up[2 * 16384] = u2;
        up[3 * 16384] = u3; up[4 * 16384] = u4; up[5 * 16384] = u5;
    }
}

// ---------------------------------------------------------------------------
// Merged input transform: img z in [0,14): z<2 -> xq; z<6 -> xkv; else xkvw
// ---------------------------------------------------------------------------
__global__ __launch_bounds__(256) void wino_in14(
    const float* __restrict__ xq, const float* __restrict__ xkv,
    const float* __restrict__ xkvw, float* __restrict__ vt)
{
    __shared__ __align__(16) float s_d[4][6][264];
    int img = blockIdx.z, ty = blockIdx.y, c4 = blockIdx.x;
    int tid = threadIdx.x;
    const float* xb;
    if (img < 2)      xb = xq   + (size_t)img * IMG;
    else if (img < 6) xb = xkv  + (size_t)(img - 2) * IMG;
    else              xb = xkvw + (size_t)(img - 6) * IMG;
    xb += (size_t)(c4 * 4) * HWSZ;

    for (int i = tid; i < 4 * 6 * 258; i += 256) {
        int c = i / (6 * 258);
        int rem = i - c * (6 * 258);
        int r = rem / 258, col = rem - r * 258;
        int gy = ty * 4 - 1 + r, gx = col - 1;
        float v = 0.f;
        if ((unsigned)gy < 256u && (unsigned)gx < 256u)
            v = xb[(size_t)c * HWSZ + gy * 256 + gx];
        s_d[c][r][col] = v;
    }
    __syncthreads();

    int tx = tid & 63, c = tid >> 6;
    float d[6][6];
#pragma unroll
    for (int r = 0; r < 6; ++r) {
        const float4* row = (const float4*)s_d[c][r];
        float4 a = row[tx], b = row[tx + 1];
        d[r][0] = a.x; d[r][1] = a.y; d[r][2] = a.z;
        d[r][3] = a.w; d[r][4] = b.x; d[r][5] = b.y;
    }
    float e[6][6];
#pragma unroll
    for (int j = 0; j < 6; ++j)
        BTCOMB(d[0][j], d[1][j], d[2][j], d[3][j], d[4][j], d[5][j],
               e[0][j], e[1][j], e[2][j], e[3][j], e[4][j], e[5][j]);

    float* dst = vt + (size_t)img * VIMG + (size_t)(c4 * 4 + c) * 4096 +
                 ty * 64 + tx;
#pragma unroll
    for (int i = 0; i < 6; ++i) {
        float o0, o1, o2, o3, o4, o5;
        BTCOMB(e[i][0], e[i][1], e[i][2], e[i][3], e[i][4], e[i][5],
               o0, o1, o2, o3, o4, o5);
        float* dp = dst + (size_t)(i * 6) * 524288;
        dp[0ull * 524288] = o0; dp[1ull * 524288] = o1; dp[2ull * 524288] = o2;
        dp[3ull * 524288] = o3; dp[4ull * 524288] = o4; dp[5ull * 524288] = o5;
    }
}

// FF-stage input transform (plain, 2 images from gQ)
__global__ __launch_bounds__(256) void wino_in(
    const float* __restrict__ x, float* __restrict__ vt)
{
    __shared__ __align__(16) float s_d[4][6][264];
    int img = blockIdx.z, ty = blockIdx.y, c4 = blockIdx.x;
    int tid = threadIdx.x;
    const float* xb = x + (size_t)img * IMG + (size_t)(c4 * 4) * HWSZ;

    for (int i = tid; i < 4 * 6 * 258; i += 256) {
        int c = i / (6 * 258);
        int rem = i - c * (6 * 258);
        int r = rem / 258, col = rem - r * 258;
        int gy = ty * 4 - 1 + r, gx = col - 1;
        float v = 0.f;
        if ((unsigned)gy < 256u && (unsigned)gx < 256u)
            v = xb[(size_t)c * HWSZ + gy * 256 + gx];
        s_d[c][r][col] = v;
    }
    __syncthreads();

    int tx = tid & 63, c = tid >> 6;
    float d[6][6];
#pragma unroll
    for (int r = 0; r < 6; ++r) {
        const float4* row = (const float4*)s_d[c][r];
        float4 a = row[tx], b = row[tx + 1];
        d[r][0] = a.x; d[r][1] = a.y; d[r][2] = a.z;
        d[r][3] = a.w; d[r][4] = b.x; d[r][5] = b.y;
    }
    float e[6][6];
#pragma unroll
    for (int j = 0; j < 6; ++j)
        BTCOMB(d[0][j], d[1][j], d[2][j], d[3][j], d[4][j], d[5][j],
               e[0][j], e[1][j], e[2][j], e[3][j], e[4][j], e[5][j]);

    float* dst = vt + (size_t)img * VIMG + (size_t)(c4 * 4 + c) * 4096 +
                 ty * 64 + tx;
#pragma unroll
    for (int i = 0; i < 6; ++i) {
        float o0, o1, o2, o3, o4, o5;
        BTCOMB(e[i][0], e[i][1], e[i][2], e[i][3], e[i][4], e[i][5],
               o0, o1, o2, o3, o4, o5);
        float* dp = dst + (size_t)(i * 6) * 524288;
        dp[0ull * 524288] = o0; dp[1ull * 524288] = o1; dp[2ull * 524288] = o2;
        dp[3ull * 524288] = o3; dp[4ull * 524288] = o4; dp[5ull * 524288] = o5;
    }
}

// ---------------------------------------------------------------------------
// Winograd GEMM (uset selects weight set; uset<0 -> per-image routing)
// Block = 256 tiles x 128 oc. Thread = 4 tiles x 32 oc. cp.async 2-stage.
// ---------------------------------------------------------------------------
__global__ __launch_bounds__(256, 1) void wino_gemm(
    const float* __restrict__ vt, const float* __restrict__ u,
    float* __restrict__ mout, int route)
{
    __shared__ __align__(16) float s_b[2][8][256];
    __shared__ __align__(16) float s_a[2][8][128];

    int pos = blockIdx.y, img = blockIdx.z, tb = blockIdx.x;
    int tid = threadIdx.x, ocs = tid >> 6, pg = tid & 63;

    int uset = route ? ((img < 2) ? 0 : 1) : 2;
    const float* B = vt + (size_t)img * VIMG + (size_t)pos * 524288 + tb * 256;
    const float* A = u + (size_t)uset * (36 * 16384) + (size_t)pos * 16384;

    uint32_t sb0 = smem_u32(&s_b[0][0][0]);
    uint32_t sa0 = smem_u32(&s_a[0][0][0]);

    int brow0 = tid >> 6, bcol0 = (tid & 63) << 2;
    int brow1 = 4 + (tid >> 6), bcol1 = bcol0;
    int arow = tid >> 5, acol = (tid & 31) << 2;

#define COPY_CHUNK(chunk, buf) do {                                        \
    int _ic0 = (chunk) * 8;                                                \
    cp16(sb0 + (buf) * 8192 + (brow0 * 256 + bcol0) * 4,                   \
         B + (size_t)(_ic0 + brow0) * 4096 + bcol0);                       \
    cp16(sb0 + (buf) * 8192 + (brow1 * 256 + bcol1) * 4,                   \
         B + (size_t)(_ic0 + brow1) * 4096 + bcol1);                       \
    cp16(sa0 + (buf) * 4096 + (arow * 128 + acol) * 4,                     \
         A + (size_t)(_ic0 + arow) * 128 + acol);                          \
    CP_COMMIT();                                                           \
} while (0)

    unsigned long long acc[4][16];
#pragma unroll
    for (int p = 0; p < 4; ++p)
#pragma unroll
        for (int j = 0; j < 16; ++j) acc[p][j] = 0ull;

    COPY_CHUNK(0, 0);

    for (int c = 0; c < 16; ++c) {
        int buf = c & 1;
        if (c < 15) {
            COPY_CHUNK(c + 1, buf ^ 1);
            CP_WAIT(1);
        } else {
            CP_WAIT(0);
        }
        __syncthreads();

#pragma unroll
        for (int ic = 0; ic < 8; ++ic) {
            unsigned long long wv[16];
            const unsigned long long* wp =
                (const unsigned long long*)&s_a[buf][ic][ocs * 32];
#pragma unroll
            for (int j = 0; j < 16; ++j) wv[j] = wp[j];
#pragma unroll
            for (int p = 0; p < 4; ++p) {
                float iv = s_b[buf][ic][pg + (p << 6)];
                unsigned long long iv2 = pack2(iv, iv);
#pragma unroll
                for (int j = 0; j < 16; ++j) ffma2(acc[p][j], iv2, wv[j]);
            }
        }
        __syncthreads();
    }

    float* Mo = mout + (size_t)img * VIMG + (size_t)pos * 524288 + tb * 256;
#pragma unroll
    for (int j = 0; j < 16; ++j) {
        int oc0 = ocs * 32 + 2 * j;
#pragma unroll
        for (int p = 0; p < 4; ++p) {
            float v0, v1;
            unpack2(acc[p][j], v0, v1);
            int t = pg + (p << 6);
            Mo[(size_t)oc0 * 4096 + t] = v0;
            Mo[(size_t)(oc0 + 1) * 4096 + t] = v1;
        }
    }
#undef COPY_CHUNK
}

// ---------------------------------------------------------------------------
// Merged output transform + bias + PReLU + residual, per-image routing.
// route=1: z<2 gQ<-xq(bq,aq); z<6 gKV<-xkv(bkv,akv); else gKVw<-xkvw(bkv,akv)
// route=0: FF stage (resid = r0, out = y0, bias0, alpha0).
// ---------------------------------------------------------------------------
__global__ __launch_bounds__(256) void wino_out14(
    const float* __restrict__ mout,
    const float* __restrict__ r0, const float* __restrict__ r1,
    const float* __restrict__ r2,
    float* __restrict__ y0, float* __restrict__ y1, float* __restrict__ y2,
    const float* __restrict__ bias0, const float* __restrict__ alpha0,
    const float* __restrict__ bias1, const float* __restrict__ alpha1,
    int route)
{
    __shared__ __align__(16) float s_o[8][4][256];
    int img = blockIdx.z, ty = blockIdx.y, og = blockIdx.x;
    int tid = threadIdx.x;

    const float* resid; float* y; const float* bias; const float* alpha;
    if (!route || img < 2) {
        resid = r0 + (size_t)img * IMG; y = y0 + (size_t)img * IMG;
        bias = bias0; alpha = alpha0;
    } else if (img < 6) {
        resid = r1 + (size_t)(img - 2) * IMG; y = y1 + (size_t)(img - 2) * IMG;
        bias = bias1; alpha = alpha1;
    } else {
        resid = r2 + (size_t)(img - 6) * IMG; y = y2 + (size_t)(img - 6) * IMG;
        bias = bias1; alpha = alpha1;
    }

#pragma unroll
    for (int it = 0; it < 2; ++it) {
        int item = tid + it * 256;
        int tx = item & 63, ol = item >> 6;
        const float* Mp = mout + (size_t)img * VIMG +
                          (size_t)(og * 8 + ol) * 4096 + ty * 64 + tx;
        float m[6][6];
#pragma unroll
        for (int pos = 0; pos < 36; ++pos)
            m[pos / 6][pos % 6] = Mp[(size_t)pos * 524288];
        float e[4][6];
#pragma unroll
        for (int j = 0; j < 6; ++j)
            ATCOMB(m[0][j], m[1][j], m[2][j], m[3][j], m[4][j], m[5][j],
                   e[0][j], e[1][j], e[2][j], e[3][j]);
#pragma unroll
        for (int r = 0; r < 4; ++r) {
            float o0, o1, o2, o3;
            ATCOMB(e[r][0], e[r][1], e[r][2], e[r][3], e[r][4], e[r][5],
                   o0, o1, o2, o3);
            ((float4*)s_o[ol][r])[tx] = make_float4(o0, o1, o2, o3);
        }
    }
    __syncthreads();

    float a = alpha[0];
    for (int i = tid; i < 8192; i += 256) {
        int ol = i >> 10, rem = i & 1023, r = rem >> 8, px = rem & 255;
        int oc = og * 8 + ol;
        int gy = ty * 4 + r;
        size_t addr = (size_t)oc * HWSZ + gy * 256 + px;
        float v = s_o[ol][r][px] + bias[oc];
        v = (v >= 0.f) ? v : a * v;
        y[addr] = resid[addr] + v;
    }
}

// ---------------------------------------------------------------------------
// Windowed dual-branch attention (register-blocked, round-4 version)
// ---------------------------------------------------------------------------
#define QST 66
#define KST 392
#define PST 66
#define VST 133
#define OST 66
#define OFF_SK (33792 / 4)
#define OFF_SV (101376 / 4)
#define OFF_SM (169472 / 4)
#define ATTN_SMEM 169728
#define NK 384

__global__ __launch_bounds__(256) void win_attn(
    float* __restrict__ Qbuf, const float* __restrict__ KV,
    const float* __restrict__ KVw, const float* __restrict__ em)
{
    extern __shared__ __align__(16) float sm[];
    float* s_q = sm;
    float* s_k = sm + OFF_SK;
    float* s_p = sm;
    float* s_v = sm + OFF_SV;
    float* s_m = sm + OFF_SM;

    int bwin = blockIdx.x;
    int bb  = bwin >> 10;
    int wy8 = ((bwin >> 5) & 31) << 3;
    int wx8 = (bwin & 31) << 3;
    int tid = threadIdx.x;
    int qb = tid >> 5;
    int kidx = tid & 31;

    float* qimg = Qbuf + (size_t)bb * IMG;
    const float* kv0 = KV + (size_t)bb * 2 * IMG;
    const float* kv1 = KVw + (size_t)bb * 4 * IMG;

    for (int i = tid; i < 64 * CC; i += 256) {
        int q = i & 63, c = i >> 6;
        int gy = wy8 + (q >> 3), gx = wx8 + (q & 7);
        s_q[c * QST + q] = qimg[(size_t)c * HWSZ + gy * WW + gx];
    }
    if (tid < 64) {
        int gy = wy8 + (tid >> 3), gx = wx8 + (tid & 7);
        s_m[tid] = em[(size_t)bb * HWSZ + gy * WW + gx];
    }

    unsigned long long accs[4][12];
#pragma unroll
    for (int p = 0; p < 4; ++p)
#pragma unroll
        for (int j = 0; j < 12; ++j) accs[p][j] = 0ull;

    for (int c0 = 0; c0 < 128; c0 += 64) {
        __syncthreads();
        for (int i = tid; i < 64 * NK; i += 256) {
            int k = i % NK, c2 = i / NK;
            const float* base;
            int t;
            if (k < 128) { base = kv0 + (size_t)(k >> 6) * IMG; t = k & 63; }
            else { int kk = k - 128; base = kv1 + (size_t)(kk >> 6) * IMG; t = kk & 63; }
            int gy = wy8 + (t >> 3), gx = wx8 + (t & 7);
            s_k[c2 * KST + k] =
                base[(size_t)(c0 + c2) * HWSZ + gy * WW + gx];
        }
        __syncthreads();

#pragma unroll 2
        for (int c2 = 0; c2 < 64; ++c2) {
            const unsigned long long* qsrc =
                (const unsigned long long*)(s_q + (c0 + c2) * QST + qb * 8);
            unsigned long long qp0 = qsrc[0], qp1 = qsrc[1],
                               qp2 = qsrc[2], qp3 = qsrc[3];
            const float* krow = s_k + c2 * KST + kidx;
#pragma unroll
            for (int j = 0; j < 12; ++j) {
                float kv = krow[32 * j];
                unsigned long long k2 = pack2(kv, kv);
                ffma2(accs[0][j], qp0, k2);
                ffma2(accs[1][j], qp1, k2);
                ffma2(accs[2][j], qp2, k2);
                ffma2(accs[3][j], qp3, k2);
            }
        }
    }

    float sreg[8][12];
#pragma unroll
    for (int p = 0; p < 4; ++p)
#pragma unroll
        for (int j = 0; j < 12; ++j)
            unpack2(accs[p][j], sreg[2 * p][j], sreg[2 * p + 1][j]);

    const float SCALE = 0.08838834764831845f;
#pragma unroll
    for (int r = 0; r < 8; ++r) {
        float msk = s_m[qb * 8 + r];
        {
            float m = sreg[r][0];
#pragma unroll
            for (int j = 1; j < 4; ++j) m = fmaxf(m, sreg[r][j]);
#pragma unroll
            for (int off = 16; off >= 1; off >>= 1)
                m = fmaxf(m, __shfl_xor_sync(0xffffffffu, m, off));
            m *= SCALE;
            float sum = 0.f;
#pragma unroll
            for (int j = 0; j < 4; ++j) {
                float e = __expf(sreg[r][j] * SCALE - m);
                sreg[r][j] = e; sum += e;
            }
#pragma unroll
            for (int off = 16; off >= 1; off >>= 1)
                sum += __shfl_xor_sync(0xffffffffu, sum, off);
            float inv = msk / sum;
#pragma unroll
            for (int j = 0; j < 4; ++j) sreg[r][j] *= inv;
        }
        {
            float m = sreg[r][4];
#pragma unroll
            for (int j = 5; j < 12; ++j) m = fmaxf(m, sreg[r][j]);
#pragma unroll
            for (int off = 16; off >= 1; off >>= 1)
                m = fmaxf(m, __shfl_xor_sync(0xffffffffu, m, off));
            m *= SCALE;
            float sum = 0.f;
#pragma unroll
            for (int j = 4; j < 12; ++j) {
                float e = __expf(sreg[r][j] * SCALE - m);
                sreg[r][j] = e; sum += e;
            }
#pragma unroll
            for (int off = 16; off >= 1; off >>= 1)
                sum += __shfl_xor_sync(0xffffffffu, sum, off);
            float inv = (1.f - msk) / sum;
#pragma unroll
            for (int j = 4; j < 12; ++j) sreg[r][j] *= inv;
        }
    }

    __syncthreads();
#pragma unroll
    for (int j = 0; j < 12; ++j) {
        int k = kidx + 32 * j;
#pragma unroll
        for (int p = 0; p < 4; ++p)
            *(unsigned long long*)(s_p + k * PST + qb * 8 + 2 * p) =
                pack2(sreg[2 * p][j], sreg[2 * p + 1][j]);
    }

    unsigned long long oacc[4][4];
#pragma unroll
    for (int p = 0; p < 4; ++p)
#pragma unroll
        for (int jc = 0; jc < 4; ++jc) oacc[p][jc] = 0ull;

    for (int kc = 0; kc < 3; ++kc) {
        __syncthreads();
        for (int i = tid; i < 128 * CC; i += 256) {
            int kk = i & 127, c = i >> 7;
            int k = kc * 128 + kk;
            const float* base;
            int t;
            if (k < 128) { base = kv0 + (size_t)(k >> 6) * IMG; t = k & 63; }
            else { int k2 = k - 128; base = kv1 + (size_t)(k2 >> 6) * IMG; t = k2 & 63; }
            int gy = wy8 + (t >> 3), gx = wx8 + (t & 7);
            s_v[kk * VST + c] = base[(size_t)c * HWSZ + gy * WW + gx];
        }
        __syncthreads();

#pragma unroll 2
        for (int kk = 0; kk < 128; ++kk) {
            int k = kc * 128 + kk;
            const unsigned long long* pp =
                (const unsigned long long*)(s_p + k * PST + qb * 8);
            unsigned long long p0 = pp[0], p1 = pp[1], p2 = pp[2], p3 = pp[3];
            const float* vrow = s_v + kk * VST + kidx;
#pragma unroll
            for (int jc = 0; jc < 4; ++jc) {
                float v = vrow[32 * jc];
                unsigned long long v2 = pack2(v, v);
                ffma2(oacc[0][jc], p0, v2);
                ffma2(oacc[1][jc], p1, v2);
                ffma2(oacc[2][jc], p2, v2);
                ffma2(oacc[3][jc], p3, v2);
            }
        }
    }

    __syncthreads();
    float* s_o = sm;
#pragma unroll
    for (int jc = 0; jc < 4; ++jc) {
        int c = kidx + 32 * jc;
#pragma unroll
        for (int p = 0; p < 4; ++p)
            *(unsigned long long*)(s_o + c * OST + qb * 8 + 2 * p) = oacc[p][jc];
    }
    __syncthreads();
    for (int i = tid; i < 64 * CC; i += 256) {
        int q = i & 63, c = i >> 6;
        int gy = wy8 + (q >> 3), gx = wx8 + (q & 7);
        qimg[(size_t)c * HWSZ + gy * WW + gx] += s_o[c * OST + q];
    }
}

// ---------------------------------------------------------------------------
extern "C" void kernel_launch(void* const* d_in, const int* in_sizes, int n_in,
                              void* d_out, int out_size)
{
    const float* xq   = (const float*)d_in[0];
    const float* xkvw = (const float*)d_in[1];
    const float* xkv  = (const float*)d_in[2];
    const float* em   = (const float*)d_in[3];
    const float* Wq   = (const float*)d_in[4];
    const float* bq   = (const float*)d_in[5];
    const float* aq   = (const float*)d_in[6];
    const float* Wkv  = (const float*)d_in[7];
    const float* bkv  = (const float*)d_in[8];
    const float* akv  = (const float*)d_in[9];
    const float* Wff  = (const float*)d_in[10];
    const float* bff  = (const float*)d_in[11];
    const float* aff  = (const float*)d_in[12];
    float* out = (float*)d_out;

    float *gQ = nullptr, *gKV = nullptr, *gKVw = nullptr;
    float *gV = nullptr, *gM = nullptr, *gU = nullptr;
    cudaGetSymbolAddress((void**)&gQ,   g_Q);
    cudaGetSymbolAddress((void**)&gKV,  g_KV);
    cudaGetSymbolAddress((void**)&gKVw, g_KVw);
    cudaGetSymbolAddress((void**)&gV,   g_V);
    cudaGetSymbolAddress((void**)&gM,   g_M);
    cudaGetSymbolAddress((void**)&gU,   g_U);

    cudaFuncSetAttribute(win_attn, cudaFuncAttributeMaxDynamicSharedMemorySize,
                         ATTN_SMEM);

    dim3 blk(256);

    // all three filter transforms, one launch
    wino_filt3<<<192, blk>>>(Wq, Wkv, Wff, gU);

    // merged front conv stages: 14 images in one in/gemm/out pipeline
    wino_in14<<<dim3(32, 64, 14), blk>>>(xq, xkv, xkvw, gV);
    wino_gemm<<<dim3(16, 36, 14), blk>>>(gV, gU, gM, 1);
    wino_out14<<<dim3(16, 64, 14), blk>>>(gM, xq, xkv, xkvw, gQ, gKV, gKVw,
                                          bq, aq, bkv, akv, 1);

    // attention (residual in place into gQ)
    win_attn<<<2048, blk, ATTN_SMEM>>>(gQ, gKV, gKVw, em);

    // FF conv stage (2 images)
    wino_in<<<dim3(32, 64, 2), blk>>>(gQ, gV);
    wino_gemm<<<dim3(16, 36, 2), blk>>>(gV, gU, gM, 0);
    wino_out14<<<dim3(16, 64, 2), blk>>>(gM, gQ, gQ, gQ, out, out, out,
                                         bff, aff, bff, aff, 0);
}